// round 1
// baseline (speedup 1.0000x reference)
#include <cuda_runtime.h>
#include <math.h>

#define B_  2
#define S_  2048
#define D_  2048
#define H_  16
#define HD_ 128
#define M_  (B_ * S_)          // 4096 flattened rows
#define BS_D (B_ * S_ * D_)

// Scratch buffers (static device globals — no allocation in kernel_launch)
__device__ float g_q[BS_D];
__device__ float g_k[BS_D];
__device__ float g_v[BS_D];
__device__ float g_ctx[BS_D];

// ---------------------------------------------------------------------------
// C[M,N] = (A[M,K] @ W[N,K]^T + bias[N]) * scale
// 128x128 block tile, BK=16, 256 threads, 8x8 per-thread microtile.
// Both A and W are K-major (row-major with K contiguous) -> NT GEMM.
// ---------------------------------------------------------------------------
__global__ __launch_bounds__(256) void gemm_nt_kernel(
    const float* __restrict__ A, const float* __restrict__ W,
    const float* __restrict__ bias, float* __restrict__ C,
    int K, float scale)
{
    __shared__ float As[16][128];
    __shared__ float Ws[16][128];

    const int tid  = threadIdx.x;
    const int row0 = blockIdx.y * 128;
    const int col0 = blockIdx.x * 128;
    const int tr   = tid >> 4;      // 0..15
    const int tc   = tid & 15;      // 0..15

    float acc[8][8];
#pragma unroll
    for (int i = 0; i < 8; i++)
#pragma unroll
        for (int j = 0; j < 8; j++) acc[i][j] = 0.f;

    const int lr = tid >> 1;        // 0..127 : tile row this thread loads
    const int lk = (tid & 1) * 8;   // 0 or 8 : k offset within BK

    for (int k0 = 0; k0 < K; k0 += 16) {
        const float* ap = &A[(size_t)(row0 + lr) * K + k0 + lk];
        float4 a0 = *(const float4*)ap;
        float4 a1 = *(const float4*)(ap + 4);
        const float* wp = &W[(size_t)(col0 + lr) * K + k0 + lk];
        float4 w0 = *(const float4*)wp;
        float4 w1 = *(const float4*)(wp + 4);

        __syncthreads();   // previous compute phase done before overwrite
        As[lk+0][lr] = a0.x; As[lk+1][lr] = a0.y; As[lk+2][lr] = a0.z; As[lk+3][lr] = a0.w;
        As[lk+4][lr] = a1.x; As[lk+5][lr] = a1.y; As[lk+6][lr] = a1.z; As[lk+7][lr] = a1.w;
        Ws[lk+0][lr] = w0.x; Ws[lk+1][lr] = w0.y; Ws[lk+2][lr] = w0.z; Ws[lk+3][lr] = w0.w;
        Ws[lk+4][lr] = w1.x; Ws[lk+5][lr] = w1.y; Ws[lk+6][lr] = w1.z; Ws[lk+7][lr] = w1.w;
        __syncthreads();

#pragma unroll
        for (int kk = 0; kk < 16; kk++) {
            float a[8], w[8];
            *(float4*)(a)     = *(const float4*)&As[kk][tr * 8];
            *(float4*)(a + 4) = *(const float4*)&As[kk][tr * 8 + 4];
            *(float4*)(w)     = *(const float4*)&Ws[kk][tc * 8];
            *(float4*)(w + 4) = *(const float4*)&Ws[kk][tc * 8 + 4];
#pragma unroll
            for (int i = 0; i < 8; i++)
#pragma unroll
                for (int j = 0; j < 8; j++)
                    acc[i][j] += a[i] * w[j];
        }
    }

#pragma unroll
    for (int i = 0; i < 8; i++) {
        const int r = row0 + tr * 8 + i;
#pragma unroll
        for (int j4 = 0; j4 < 8; j4 += 4) {
            const int c = col0 + tc * 8 + j4;
            float4 o;
            o.x = (acc[i][j4+0] + bias[c+0]) * scale;
            o.y = (acc[i][j4+1] + bias[c+1]) * scale;
            o.z = (acc[i][j4+2] + bias[c+2]) * scale;
            o.w = (acc[i][j4+3] + bias[c+3]) * scale;
            *(float4*)&C[(size_t)r * D_ + c] = o;
        }
    }
}

// ---------------------------------------------------------------------------
// Flash attention, causal. One block = (64 q rows) x (one head) x (one batch).
// Tiles over kv in steps of 64, online softmax, O accumulators in registers.
// Q/K stored d-major (transposed) in smem for conflict-free S=QK^T compute.
// ---------------------------------------------------------------------------
#define QK_PAD 68              // 64 rows padded to 68 (16B aligned, bank-safe)
#define SS_PAD 65

#define SMEM_FLOATS (2 * 128 * QK_PAD + 64 * 128 + 64 * SS_PAD + 3 * 64)
#define SMEM_BYTES  (SMEM_FLOATS * 4)

__global__ __launch_bounds__(256) void attn_kernel()
{
    extern __shared__ float smem[];
    float (*Qs)[QK_PAD] = (float(*)[QK_PAD])(smem);
    float (*Ks)[QK_PAD] = (float(*)[QK_PAD])(smem + 128 * QK_PAD);
    float (*Vs)[128]    = (float(*)[128])   (smem + 2 * 128 * QK_PAD);
    float (*Ss)[SS_PAD] = (float(*)[SS_PAD])(smem + 2 * 128 * QK_PAD + 64 * 128);
    float* mrow = smem + 2 * 128 * QK_PAD + 64 * 128 + 64 * SS_PAD;
    float* lrow = mrow + 64;
    float* srow = lrow + 64;

    const int tid = threadIdx.x;
    const int q0  = blockIdx.x * 64;
    const int h   = blockIdx.y;
    const int b   = blockIdx.z;
    const size_t base = (size_t)b * S_ * D_ + (size_t)h * HD_;

    // Load Q tile [64 rows x 128 d], store transposed Qs[d][r]
#pragma unroll
    for (int it = 0; it < 8; it++) {
        int id = tid + it * 256;          // float4 index 0..2047
        int r  = id >> 5;                 // 0..63
        int d  = (id & 31) * 4;           // 0..124
        float4 qv = *(const float4*)&g_q[base + (size_t)(q0 + r) * D_ + d];
        Qs[d+0][r] = qv.x; Qs[d+1][r] = qv.y; Qs[d+2][r] = qv.z; Qs[d+3][r] = qv.w;
    }
    if (tid < 64) { mrow[tid] = -1e30f; lrow[tid] = 0.f; }

    const int rg = tid >> 4;              // 0..15 -> 4 q rows each
    const int cg = tid & 15;              // 0..15
    const int r0 = rg * 4;
    const int c0 = cg * 4;                // S-frag cols
    const int co = cg * 8;                // O-frag cols

    float oacc[4][8];
#pragma unroll
    for (int i = 0; i < 4; i++)
#pragma unroll
        for (int j = 0; j < 8; j++) oacc[i][j] = 0.f;

    const int ntiles = q0 / 64 + 1;       // causal: kv tiles [0, q0+64)
    for (int t = 0; t < ntiles; t++) {
        const int kv0 = t * 64;
        __syncthreads();  // Q stores (iter 0) / prev PV reads done before K/V overwrite

        // Load K transposed, V natural
#pragma unroll
        for (int it = 0; it < 8; it++) {
            int id = tid + it * 256;
            int r  = id >> 5;
            int d  = (id & 31) * 4;
            float4 kv4 = *(const float4*)&g_k[base + (size_t)(kv0 + r) * D_ + d];
            Ks[d+0][r] = kv4.x; Ks[d+1][r] = kv4.y; Ks[d+2][r] = kv4.z; Ks[d+3][r] = kv4.w;
            float4 vv  = *(const float4*)&g_v[base + (size_t)(kv0 + r) * D_ + d];
            *(float4*)&Vs[r][d] = vv;
        }
        __syncthreads();

        // S = Q @ K^T  (4x4 frag per thread)
        float sacc[4][4];
#pragma unroll
        for (int i = 0; i < 4; i++)
#pragma unroll
            for (int j = 0; j < 4; j++) sacc[i][j] = 0.f;

#pragma unroll 4
        for (int d = 0; d < 128; d++) {
            float4 qv = *(const float4*)&Qs[d][r0];
            float4 kv = *(const float4*)&Ks[d][c0];
            const float qa[4] = {qv.x, qv.y, qv.z, qv.w};
            const float ka[4] = {kv.x, kv.y, kv.z, kv.w};
#pragma unroll
            for (int i = 0; i < 4; i++)
#pragma unroll
                for (int j = 0; j < 4; j++)
                    sacc[i][j] += qa[i] * ka[j];
        }
#pragma unroll
        for (int i = 0; i < 4; i++)
#pragma unroll
            for (int j = 0; j < 4; j++)
                Ss[r0 + i][c0 + j] = sacc[i][j];
        __syncthreads();

        // Online softmax: one thread per q row
        if (tid < 64) {
            const int r = tid;
            const int limit = q0 + r - kv0;           // causal: c <= limit valid
            const int cmax  = limit < 63 ? limit : 63;
            float m = mrow[r];
            float mx = m;
            for (int c = 0; c <= cmax; c++) mx = fmaxf(mx, Ss[r][c]);
            const float sc = __expf(m - mx);
            float sum = 0.f;
#pragma unroll 4
            for (int c = 0; c < 64; c++) {
                float p = (c <= cmax) ? __expf(Ss[r][c] - mx) : 0.f;
                Ss[r][c] = p;
                sum += p;
            }
            mrow[r] = mx;
            lrow[r] = lrow[r] * sc + sum;
            srow[r] = sc;
        }
        __syncthreads();

        // Rescale O, accumulate P @ V
        float scl[4];
#pragma unroll
        for (int i = 0; i < 4; i++) scl[i] = srow[r0 + i];
#pragma unroll
        for (int i = 0; i < 4; i++)
#pragma unroll
            for (int j = 0; j < 8; j++) oacc[i][j] *= scl[i];

#pragma unroll 2
        for (int kv = 0; kv < 64; kv++) {
            float p[4];
#pragma unroll
            for (int i = 0; i < 4; i++) p[i] = Ss[r0 + i][kv];
            float4 v0 = *(const float4*)&Vs[kv][co];
            float4 v1 = *(const float4*)&Vs[kv][co + 4];
            const float va[8] = {v0.x, v0.y, v0.z, v0.w, v1.x, v1.y, v1.z, v1.w};
#pragma unroll
            for (int i = 0; i < 4; i++)
#pragma unroll
                for (int j = 0; j < 8; j++)
                    oacc[i][j] += p[i] * va[j];
        }
    }

    // Normalize and write context in [B, S, H*HD] layout
    float inv[4];
#pragma unroll
    for (int i = 0; i < 4; i++) inv[i] = 1.f / lrow[r0 + i];
#pragma unroll
    for (int i = 0; i < 4; i++) {
        const size_t rowbase = base + (size_t)(q0 + r0 + i) * D_ + co;
        float4 o0, o1;
        o0.x = oacc[i][0] * inv[i]; o0.y = oacc[i][1] * inv[i];
        o0.z = oacc[i][2] * inv[i]; o0.w = oacc[i][3] * inv[i];
        o1.x = oacc[i][4] * inv[i]; o1.y = oacc[i][5] * inv[i];
        o1.z = oacc[i][6] * inv[i]; o1.w = oacc[i][7] * inv[i];
        *(float4*)&g_ctx[rowbase]     = o0;
        *(float4*)&g_ctx[rowbase + 4] = o1;
    }
}

// ---------------------------------------------------------------------------
extern "C" void kernel_launch(void* const* d_in, const int* in_sizes, int n_in,
                              void* d_out, int out_size)
{
    const float* x  = (const float*)d_in[0];
    const float* Wq = (const float*)d_in[1];
    const float* bq = (const float*)d_in[2];
    const float* Wk = (const float*)d_in[3];
    const float* bk = (const float*)d_in[4];
    const float* Wv = (const float*)d_in[5];
    const float* bv = (const float*)d_in[6];
    const float* Wo = (const float*)d_in[7];
    const float* bo = (const float*)d_in[8];
    float* out = (float*)d_out;

    float *qp, *kp, *vp, *cp;
    cudaGetSymbolAddress((void**)&qp, g_q);
    cudaGetSymbolAddress((void**)&kp, g_k);
    cudaGetSymbolAddress((void**)&vp, g_v);
    cudaGetSymbolAddress((void**)&cp, g_ctx);

    cudaFuncSetAttribute(attn_kernel,
                         cudaFuncAttributeMaxDynamicSharedMemorySize, SMEM_BYTES);

    const dim3 gg(D_ / 128, M_ / 128);   // (16, 32) blocks
    const float qscale = 0.08838834764831845f;  // 1/sqrt(HD)

    gemm_nt_kernel<<<gg, 256>>>(x, Wq, bq, qp, D_, qscale);
    gemm_nt_kernel<<<gg, 256>>>(x, Wk, bk, kp, D_, 1.f);
    gemm_nt_kernel<<<gg, 256>>>(x, Wv, bv, vp, D_, 1.f);

    const dim3 ga(S_ / 64, H_, B_);      // (32, 16, 2) blocks
    attn_kernel<<<ga, 256, SMEM_BYTES>>>();

    gemm_nt_kernel<<<gg, 256>>>(cp, Wo, bo, out, D_, 1.f);
}

// round 4
// speedup vs baseline: 1.8248x; 1.8248x over previous
#include <cuda_runtime.h>
#include <cstdint>
#include <math.h>

#define B_  2
#define S_  2048
#define D_  2048
#define H_  16
#define HD_ 128
#define M_  (B_ * S_)
#define BS_D (B_ * S_ * D_)
#define WSZ (D_ * D_)
#define LOG2E 1.4426950408889634f

// Scratch (device globals — no allocation allowed)
__device__ float g_xh[BS_D], g_xl[BS_D];
__device__ float g_wh[4 * WSZ], g_wl[4 * WSZ];
__device__ float g_q[BS_D], g_k[BS_D], g_v[BS_D];
__device__ float g_ch[BS_D], g_cl[BS_D];

// ===================== helpers =====================
__device__ __forceinline__ float to_tf32(float x) {
    float y;
    asm("cvt.rna.tf32.f32 %0, %1;" : "=f"(y) : "f"(x));
    return y;
}
__device__ __forceinline__ void cp16(uint32_t dst, const void* src) {
    asm volatile("cp.async.cg.shared.global [%0], [%1], 16;"
                 :: "r"(dst), "l"(src) : "memory");
}
#define CP_COMMIT() asm volatile("cp.async.commit_group;" ::: "memory")
#define CP_WAIT0()  asm volatile("cp.async.wait_group 0;" ::: "memory")

// m16n8k8 tf32: A row-major a0(r=l>>2,k=l&3) a1(r+8) a2(k+4) a3(r+8,k+4)
//               B col-major b0(k=l&3,n=l>>2) b1(k+4)
//               C c0(r,2c) c1(r,2c+1) c2(r+8,2c) c3(r+8,2c+1), c=l&3
__device__ __forceinline__ void mma8(float* d, const uint32_t* a, const uint32_t* b) {
    asm volatile("mma.sync.aligned.m16n8k8.row.col.f32.tf32.tf32.f32 "
                 "{%0,%1,%2,%3}, {%4,%5,%6,%7}, {%8,%9}, {%0,%1,%2,%3};"
                 : "+f"(d[0]), "+f"(d[1]), "+f"(d[2]), "+f"(d[3])
                 : "r"(a[0]), "r"(a[1]), "r"(a[2]), "r"(a[3]),
                   "r"(b[0]), "r"(b[1]));
}

// fast exp2 on FMA pipe, rel err ~2e-6; input clamped at -126
__device__ __forceinline__ float exp2f_fast(float z) {
    z = fmaxf(z, -126.f);
    float r = z + 12582912.f;            // 1.5*2^23 round-to-int trick
    int   n = __float_as_int(r);
    float f = z - (r - 12582912.f);      // [-0.5, 0.5]
    float p = 1.3333558146e-3f;
    p = fmaf(p, f, 9.6180216e-3f);
    p = fmaf(p, f, 5.5504109e-2f);
    p = fmaf(p, f, 2.4022651e-1f);
    p = fmaf(p, f, 6.9314718e-1f);
    p = fmaf(p, f, 1.0f);
    return __int_as_float(__float_as_int(p) + (n << 23));
}

// ===================== prepass: tf32 hi/lo split =====================
__global__ __launch_bounds__(256) void split_k(const float* __restrict__ src,
                                               float* __restrict__ hi,
                                               float* __restrict__ lo, int n4) {
    int i = blockIdx.x * 256 + threadIdx.x;
    if (i >= n4) return;
    float4 v = ((const float4*)src)[i];
    float4 h, l;
    h.x = to_tf32(v.x); l.x = to_tf32(v.x - h.x);
    h.y = to_tf32(v.y); l.y = to_tf32(v.y - h.y);
    h.z = to_tf32(v.z); l.z = to_tf32(v.z - h.z);
    h.w = to_tf32(v.w); l.w = to_tf32(v.w - h.w);
    ((float4*)hi)[i] = h;
    ((float4*)lo)[i] = l;
}

// ===================== split-tf32 GEMM =====================
// C[M,N] = (A @ W^T + bias) * scale, A=Ah+Al, W=Wh+Wl, 3-term mma.
// 128x128 tile, k-chunk 32, 8 warps (2x4), double-buffered cp.async.
#define G_STR   36
#define G_TILE  (128 * G_STR)
#define G_STAGE (4 * G_TILE)
#define G_SMEM  ((2 * G_STAGE + 128) * 4)

__global__ __launch_bounds__(256) void gemm_split(
    const float* __restrict__ Ah, const float* __restrict__ Al,
    const float* __restrict__ Wh, const float* __restrict__ Wl,
    const float* __restrict__ bias, float* __restrict__ C,
    float scale, int doRound)
{
    extern __shared__ float sm[];
    float* bias_s = sm + 2 * G_STAGE;
    const int tid = threadIdx.x, lane = tid & 31, wid = tid >> 5;
    const int row0 = blockIdx.y * 128, col0 = blockIdx.x * 128;
    const uint32_t sbase = (uint32_t)__cvta_generic_to_shared(sm);
    const int m0w = (wid >> 2) * 64, n0w = (wid & 3) * 32;

    if (tid < 128) bias_s[tid] = bias[col0 + tid];

    float acc[4][4][4];
#pragma unroll
    for (int a = 0; a < 4; a++)
#pragma unroll
        for (int b = 0; b < 4; b++)
#pragma unroll
            for (int c = 0; c < 4; c++) acc[a][b][c] = 0.f;

    const float* srcs[4] = {Ah, Al, Wh, Wl};
    const int rbase[4] = {row0, row0, col0, col0};

    // prologue chunk 0 -> stage 0
#pragma unroll
    for (int tl = 0; tl < 4; tl++) {
#pragma unroll
        for (int j = 0; j < 4; j++) {
            int id = tid + 256 * j, r = id >> 3, c4 = id & 7;
            cp16(sbase + (uint32_t)(tl * G_TILE + r * G_STR + c4 * 4) * 4u,
                 srcs[tl] + (size_t)(rbase[tl] + r) * D_ + c4 * 4);
        }
    }
    CP_COMMIT();

    for (int ch = 0; ch < D_ / 32; ch++) {
        const int s = ch & 1;
        CP_WAIT0();
        __syncthreads();
        if (ch + 1 < D_ / 32) {
            const uint32_t so = (uint32_t)((s ^ 1) * G_STAGE) * 4u;
            const int k1 = (ch + 1) * 32;
#pragma unroll
            for (int tl = 0; tl < 4; tl++) {
#pragma unroll
                for (int j = 0; j < 4; j++) {
                    int id = tid + 256 * j, r = id >> 3, c4 = id & 7;
                    cp16(sbase + so + (uint32_t)(tl * G_TILE + r * G_STR + c4 * 4) * 4u,
                         srcs[tl] + (size_t)(rbase[tl] + r) * D_ + k1 + c4 * 4);
                }
            }
            CP_COMMIT();
        }
        const float* sAh = sm + s * G_STAGE;
        const float* sAl = sAh + G_TILE;
        const float* sBh = sAl + G_TILE;
        const float* sBl = sBh + G_TILE;

#pragma unroll
        for (int ks = 0; ks < 4; ks++) {
            const int kb = ks * 8;
            uint32_t ah[4][4], al[4][4], bh[4][2], bl[4][2];
#pragma unroll
            for (int mt = 0; mt < 4; mt++) {
                const int m = m0w + mt * 16 + (lane >> 2);
                const int k = kb + (lane & 3);
                ah[mt][0] = __float_as_uint(sAh[m * G_STR + k]);
                ah[mt][1] = __float_as_uint(sAh[(m + 8) * G_STR + k]);
                ah[mt][2] = __float_as_uint(sAh[m * G_STR + k + 4]);
                ah[mt][3] = __float_as_uint(sAh[(m + 8) * G_STR + k + 4]);
                al[mt][0] = __float_as_uint(sAl[m * G_STR + k]);
                al[mt][1] = __float_as_uint(sAl[(m + 8) * G_STR + k]);
                al[mt][2] = __float_as_uint(sAl[m * G_STR + k + 4]);
                al[mt][3] = __float_as_uint(sAl[(m + 8) * G_STR + k + 4]);
            }
#pragma unroll
            for (int nt = 0; nt < 4; nt++) {
                const int n = n0w + nt * 8 + (lane >> 2);
                const int k = kb + (lane & 3);
                bh[nt][0] = __float_as_uint(sBh[n * G_STR + k]);
                bh[nt][1] = __float_as_uint(sBh[n * G_STR + k + 4]);
                bl[nt][0] = __float_as_uint(sBl[n * G_STR + k]);
                bl[nt][1] = __float_as_uint(sBl[n * G_STR + k + 4]);
            }
#pragma unroll
            for (int mt = 0; mt < 4; mt++)
#pragma unroll
                for (int nt = 0; nt < 4; nt++) {
                    mma8(acc[mt][nt], ah[mt], bh[nt]);
                    mma8(acc[mt][nt], al[mt], bh[nt]);
                    mma8(acc[mt][nt], ah[mt], bl[nt]);
                }
        }
    }

#pragma unroll
    for (int mt = 0; mt < 4; mt++) {
        const int r = row0 + m0w + mt * 16 + (lane >> 2);
#pragma unroll
        for (int nt = 0; nt < 4; nt++) {
            const int cc = n0w + nt * 8 + 2 * (lane & 3);
            float v0 = (acc[mt][nt][0] + bias_s[cc]) * scale;
            float v1 = (acc[mt][nt][1] + bias_s[cc + 1]) * scale;
            float v2 = (acc[mt][nt][2] + bias_s[cc]) * scale;
            float v3 = (acc[mt][nt][3] + bias_s[cc + 1]) * scale;
            if (doRound) {
                v0 = to_tf32(v0); v1 = to_tf32(v1);
                v2 = to_tf32(v2); v3 = to_tf32(v3);
            }
            *(float2*)&C[(size_t)r * D_ + col0 + cc] = make_float2(v0, v1);
            *(float2*)&C[(size_t)(r + 8) * D_ + col0 + cc] = make_float2(v2, v3);
        }
    }
}

// ===================== mma flash attention =====================
// CTA: 128 q rows x (head, batch); kv tiles 64, double-buffered; causal.
#define QS(r, c) (A_QS + (r) * 128 + ((c) ^ (((r) & 7) << 2)))
#define KS(st, r, c) (A_KS + (st) * 8192 + (r) * 128 + ((c) ^ (((r) & 7) << 2)))
#define VS(st, r, c) (A_VS + (st) * 8192 + (r) * 128 + ((c) ^ (((r) & 7) << 2)))
#define SS(r, c) (A_SS + (r) * 64 + ((c) ^ (((r) & 7) << 2)))
#define A_QS 0
#define A_KS 16384
#define A_VS 32768
#define A_SS 49152
#define A_MR 57344
#define A_LR 57472
#define A_SR 57600
#define ATTN_SMEM (57728 * 4)

__global__ __launch_bounds__(256) void attn_tc()
{
    extern __shared__ float sm[];
    const int tid = threadIdx.x, lane = tid & 31, wid = tid >> 5;
    const int wR = wid >> 1, wC = wid & 1;
    const int q0 = blockIdx.x * 128, h = blockIdx.y, b = blockIdx.z;
    const uint32_t sbase = (uint32_t)__cvta_generic_to_shared(sm);
    const size_t gbase = (size_t)b * S_ * D_ + (size_t)h * HD_;

    if (tid < 128) { sm[A_MR + tid] = -1e30f; sm[A_LR + tid] = 0.f; }

    // prologue: Q (128x128) + K0,V0 (64x128)
#pragma unroll
    for (int j = 0; j < 16; j++) {
        int id = tid + 256 * j, r = id >> 5, c4 = id & 31;
        cp16(sbase + (uint32_t)QS(r, c4 * 4) * 4u,
             &g_q[gbase + (size_t)(q0 + r) * D_ + c4 * 4]);
    }
#pragma unroll
    for (int j = 0; j < 8; j++) {
        int id = tid + 256 * j, r = id >> 5, c4 = id & 31;
        cp16(sbase + (uint32_t)KS(0, r, c4 * 4) * 4u,
             &g_k[gbase + (size_t)r * D_ + c4 * 4]);
        cp16(sbase + (uint32_t)VS(0, r, c4 * 4) * 4u,
             &g_v[gbase + (size_t)r * D_ + c4 * 4]);
    }
    CP_COMMIT();

    float oacc[2][8][4];
#pragma unroll
    for (int a = 0; a < 2; a++)
#pragma unroll
        for (int c = 0; c < 8; c++)
#pragma unroll
            for (int e = 0; e < 4; e++) oacc[a][c][e] = 0.f;

    const int ntiles = q0 / 64 + 2;
    for (int t = 0; t < ntiles; t++) {
        const int s = t & 1;
        const int kv0 = t * 64;
        CP_WAIT0();
        __syncthreads();
        if (t + 1 < ntiles) {
            const size_t kr = gbase + (size_t)(kv0 + 64) * D_;
#pragma unroll
            for (int j = 0; j < 8; j++) {
                int id = tid + 256 * j, r = id >> 5, c4 = id & 31;
                cp16(sbase + (uint32_t)KS(s ^ 1, r, c4 * 4) * 4u,
                     &g_k[kr + (size_t)r * D_ + c4 * 4]);
                cp16(sbase + (uint32_t)VS(s ^ 1, r, c4 * 4) * 4u,
                     &g_v[kr + (size_t)r * D_ + c4 * 4]);
            }
            CP_COMMIT();
        }

        // ---- S = Q K^T ----
        float sacc[2][4][4];
#pragma unroll
        for (int a = 0; a < 2; a++)
#pragma unroll
            for (int c = 0; c < 4; c++)
#pragma unroll
                for (int e = 0; e < 4; e++) sacc[a][c][e] = 0.f;

#pragma unroll
        for (int ks = 0; ks < 16; ks++) {
            const int kb = ks * 8, k = kb + (lane & 3);
            uint32_t aq[2][4], bk[4][2];
#pragma unroll
            for (int mt = 0; mt < 2; mt++) {
                const int r = wR * 32 + mt * 16 + (lane >> 2);
                aq[mt][0] = __float_as_uint(sm[QS(r, k)]);
                aq[mt][1] = __float_as_uint(sm[QS(r + 8, k)]);
                aq[mt][2] = __float_as_uint(sm[QS(r, k + 4)]);
                aq[mt][3] = __float_as_uint(sm[QS(r + 8, k + 4)]);
            }
#pragma unroll
            for (int nt = 0; nt < 4; nt++) {
                const int n = wC * 32 + nt * 8 + (lane >> 2);
                bk[nt][0] = __float_as_uint(sm[KS(s, n, k)]);
                bk[nt][1] = __float_as_uint(sm[KS(s, n, k + 4)]);
            }
#pragma unroll
            for (int mt = 0; mt < 2; mt++)
#pragma unroll
                for (int nt = 0; nt < 4; nt++)
                    mma8(sacc[mt][nt], aq[mt], bk[nt]);
        }

        // masked store S -> Ss
#pragma unroll
        for (int mt = 0; mt < 2; mt++) {
            const int rl = wR * 32 + mt * 16 + (lane >> 2);
#pragma unroll
            for (int nt = 0; nt < 4; nt++) {
                const int cl_ = wC * 32 + nt * 8 + 2 * (lane & 3);
                float e0 = (kv0 + cl_     <= q0 + rl)     ? sacc[mt][nt][0] : -1e30f;
                float e1 = (kv0 + cl_ + 1 <= q0 + rl)     ? sacc[mt][nt][1] : -1e30f;
                float e2 = (kv0 + cl_     <= q0 + rl + 8) ? sacc[mt][nt][2] : -1e30f;
                float e3 = (kv0 + cl_ + 1 <= q0 + rl + 8) ? sacc[mt][nt][3] : -1e30f;
                *(float2*)&sm[SS(rl, cl_)]     = make_float2(e0, e1);
                *(float2*)&sm[SS(rl + 8, cl_)] = make_float2(e2, e3);
            }
        }
        __syncthreads();

        // ---- online softmax: 2 threads per row, FMA-pipe exp ----
        {
            const int r = tid >> 1, cb = (tid & 1) * 32;
            float mx = -1e30f;
#pragma unroll
            for (int i = 0; i < 8; i++) {
                float4 v = *(const float4*)&sm[SS(r, cb + i * 4)];
                mx = fmaxf(mx, fmaxf(fmaxf(v.x, v.y), fmaxf(v.z, v.w)));
            }
            mx = fmaxf(mx, __shfl_xor_sync(0xffffffffu, mx, 1));
            const float mold = sm[A_MR + r];
            const float mnew = fmaxf(mold, mx);
            const float msl  = mnew * LOG2E;
            float sum = 0.f;
#pragma unroll
            for (int i = 0; i < 8; i++) {
                float4 v = *(const float4*)&sm[SS(r, cb + i * 4)];
                v.x = to_tf32(exp2f_fast(fmaf(v.x, LOG2E, -msl)));
                v.y = to_tf32(exp2f_fast(fmaf(v.y, LOG2E, -msl)));
                v.z = to_tf32(exp2f_fast(fmaf(v.z, LOG2E, -msl)));
                v.w = to_tf32(exp2f_fast(fmaf(v.w, LOG2E, -msl)));
                *(float4*)&sm[SS(r, cb + i * 4)] = v;
                sum += v.x + v.y + v.z + v.w;
            }
            sum += __shfl_xor_sync(0xffffffffu, sum, 1);
            if ((tid & 1) == 0) {
                const float scl = exp2f_fast((mold - mnew) * LOG2E);
                sm[A_MR + r] = mnew;
                sm[A_SR + r] = scl;
                sm[A_LR + r] = sm[A_LR + r] * scl + sum;
            }
        }
        __syncthreads();

        // ---- rescale O, PV mma ----
#pragma unroll
        for (int mt = 0; mt < 2; mt++) {
            const int rl = wR * 32 + mt * 16 + (lane >> 2);
            const float s0 = sm[A_SR + rl], s1 = sm[A_SR + rl + 8];
#pragma unroll
            for (int nt = 0; nt < 8; nt++) {
                oacc[mt][nt][0] *= s0; oacc[mt][nt][1] *= s0;
                oacc[mt][nt][2] *= s1; oacc[mt][nt][3] *= s1;
            }
        }
#pragma unroll
        for (int ks = 0; ks < 8; ks++) {
            const int kb = ks * 8, k = kb + (lane & 3);
            uint32_t ap[2][4], bv[8][2];
#pragma unroll
            for (int mt = 0; mt < 2; mt++) {
                const int r = wR * 32 + mt * 16 + (lane >> 2);
                ap[mt][0] = __float_as_uint(sm[SS(r, k)]);
                ap[mt][1] = __float_as_uint(sm[SS(r + 8, k)]);
                ap[mt][2] = __float_as_uint(sm[SS(r, k + 4)]);
                ap[mt][3] = __float_as_uint(sm[SS(r + 8, k + 4)]);
            }
#pragma unroll
            for (int nt = 0; nt < 8; nt++) {
                const int n = wC * 64 + nt * 8 + (lane >> 2);
                bv[nt][0] = __float_as_uint(sm[VS(s, k, n)]);
                bv[nt][1] = __float_as_uint(sm[VS(s, k + 4, n)]);
            }
#pragma unroll
            for (int mt = 0; mt < 2; mt++)
#pragma unroll
                for (int nt = 0; nt < 8; nt++)
                    mma8(oacc[mt][nt], ap[mt], bv[nt]);
        }
    }

    // epilogue: normalize, split hi/lo, write ctx
#pragma unroll
    for (int mt = 0; mt < 2; mt++) {
        const int rl = wR * 32 + mt * 16 + (lane >> 2);
        const float i0 = 1.f / sm[A_LR + rl], i1 = 1.f / sm[A_LR + rl + 8];
        const size_t r0a = gbase + (size_t)(q0 + rl) * D_;
        const size_t r1a = gbase + (size_t)(q0 + rl + 8) * D_;
#pragma unroll
        for (int nt = 0; nt < 8; nt++) {
            const int dd = wC * 64 + nt * 8 + 2 * (lane & 3);
            float v0 = oacc[mt][nt][0] * i0, v1 = oacc[mt][nt][1] * i0;
            float v2 = oacc[mt][nt][2] * i1, v3 = oacc[mt][nt][3] * i1;
            float h0 = to_tf32(v0), h1 = to_tf32(v1);
            float h2 = to_tf32(v2), h3 = to_tf32(v3);
            *(float2*)&g_ch[r0a + dd] = make_float2(h0, h1);
            *(float2*)&g_ch[r1a + dd] = make_float2(h2, h3);
            *(float2*)&g_cl[r0a + dd] = make_float2(to_tf32(v0 - h0), to_tf32(v1 - h1));
            *(float2*)&g_cl[r1a + dd] = make_float2(to_tf32(v2 - h2), to_tf32(v3 - h3));
        }
    }
}

// ===================== launcher =====================
extern "C" void kernel_launch(void* const* d_in, const int* in_sizes, int n_in,
                              void* d_out, int out_size)
{
    const float* x  = (const float*)d_in[0];
    const float* Wq = (const float*)d_in[1];
    const float* bq = (const float*)d_in[2];
    const float* Wk = (const float*)d_in[3];
    const float* bk = (const float*)d_in[4];
    const float* Wv = (const float*)d_in[5];
    const float* bv = (const float*)d_in[6];
    const float* Wo = (const float*)d_in[7];
    const float* bo = (const float*)d_in[8];
    float* out = (float*)d_out;

    float *xh, *xl, *wh, *wl, *qp, *kp, *vp, *chp, *clp;
    cudaGetSymbolAddress((void**)&xh, g_xh);
    cudaGetSymbolAddress((void**)&xl, g_xl);
    cudaGetSymbolAddress((void**)&wh, g_wh);
    cudaGetSymbolAddress((void**)&wl, g_wl);
    cudaGetSymbolAddress((void**)&qp, g_q);
    cudaGetSymbolAddress((void**)&kp, g_k);
    cudaGetSymbolAddress((void**)&vp, g_v);
    cudaGetSymbolAddress((void**)&chp, g_ch);
    cudaGetSymbolAddress((void**)&clp, g_cl);

    cudaFuncSetAttribute(gemm_split,
                         cudaFuncAttributeMaxDynamicSharedMemorySize, G_SMEM);
    cudaFuncSetAttribute(attn_tc,
                         cudaFuncAttributeMaxDynamicSharedMemorySize, ATTN_SMEM);

    // hi/lo prepass
    split_k<<<(BS_D / 4 + 255) / 256, 256>>>(x, xh, xl, BS_D / 4);
    split_k<<<(WSZ / 4 + 255) / 256, 256>>>(Wq, wh + 0 * WSZ, wl + 0 * WSZ, WSZ / 4);
    split_k<<<(WSZ / 4 + 255) / 256, 256>>>(Wk, wh + 1 * WSZ, wl + 1 * WSZ, WSZ / 4);
    split_k<<<(WSZ / 4 + 255) / 256, 256>>>(Wv, wh + 2 * WSZ, wl + 2 * WSZ, WSZ / 4);
    split_k<<<(WSZ / 4 + 255) / 256, 256>>>(Wo, wh + 3 * WSZ, wl + 3 * WSZ, WSZ / 4);

    const dim3 gg(D_ / 128, M_ / 128);            // (16, 32)
    const float qscale = 0.08838834764831845f;    // 1/sqrt(HD)
    gemm_split<<<gg, 256, G_SMEM>>>(xh, xl, wh + 0 * WSZ, wl + 0 * WSZ, bq, qp, qscale, 1);
    gemm_split<<<gg, 256, G_SMEM>>>(xh, xl, wh + 1 * WSZ, wl + 1 * WSZ, bk, kp, 1.f, 1);
    gemm_split<<<gg, 256, G_SMEM>>>(xh, xl, wh + 2 * WSZ, wl + 2 * WSZ, bv, vp, 1.f, 1);

    const dim3 ga(S_ / 128, H_, B_);              // (16, 16, 2)
    attn_tc<<<ga, 256, ATTN_SMEM>>>();

    gemm_split<<<gg, 256, G_SMEM>>>(chp, clp, wh + 3 * WSZ, wl + 3 * WSZ, bo, out, 1.f, 0);
}

// round 5
// speedup vs baseline: 3.0764x; 1.6859x over previous
#include <cuda_runtime.h>
#include <cuda_bf16.h>
#include <cstdint>
#include <math.h>

#define B_  2
#define S_  2048
#define D_  2048
#define H_  16
#define HD_ 128
#define M_  (B_ * S_)
#define BS_D (B_ * S_ * D_)
#define WSZ (D_ * D_)
#define LOG2E 1.4426950408889634f

// Scratch (device globals — no allocation allowed)
__device__ __align__(16) __nv_bfloat16 g_xh[BS_D], g_xl[BS_D];
__device__ __align__(16) __nv_bfloat16 g_wh[4 * WSZ], g_wl[4 * WSZ];
__device__ __align__(16) float g_q[BS_D], g_k[BS_D], g_v[BS_D];
__device__ __align__(16) __nv_bfloat16 g_ch[BS_D], g_cl[BS_D];

// ===================== helpers =====================
__device__ __forceinline__ float to_tf32(float x) {
    float y;
    asm("cvt.rna.tf32.f32 %0, %1;" : "=f"(y) : "f"(x));
    return y;
}
__device__ __forceinline__ void cp16(uint32_t dst, const void* src) {
    asm volatile("cp.async.cg.shared.global [%0], [%1], 16;"
                 :: "r"(dst), "l"(src) : "memory");
}
#define CP_COMMIT() asm volatile("cp.async.commit_group;" ::: "memory")
#define CP_WAIT0()  asm volatile("cp.async.wait_group 0;" ::: "memory")

// tf32 m16n8k8 (attention)
__device__ __forceinline__ void mma8(float* d, const uint32_t* a, const uint32_t* b) {
    asm volatile("mma.sync.aligned.m16n8k8.row.col.f32.tf32.tf32.f32 "
                 "{%0,%1,%2,%3}, {%4,%5,%6,%7}, {%8,%9}, {%0,%1,%2,%3};"
                 : "+f"(d[0]), "+f"(d[1]), "+f"(d[2]), "+f"(d[3])
                 : "r"(a[0]), "r"(a[1]), "r"(a[2]), "r"(a[3]),
                   "r"(b[0]), "r"(b[1]));
}
// bf16 m16n8k16 (GEMMs)
__device__ __forceinline__ void mma16(float* d, const uint32_t* a, const uint32_t* b) {
    asm volatile("mma.sync.aligned.m16n8k16.row.col.f32.bf16.bf16.f32 "
                 "{%0,%1,%2,%3}, {%4,%5,%6,%7}, {%8,%9}, {%0,%1,%2,%3};"
                 : "+f"(d[0]), "+f"(d[1]), "+f"(d[2]), "+f"(d[3])
                 : "r"(a[0]), "r"(a[1]), "r"(a[2]), "r"(a[3]),
                   "r"(b[0]), "r"(b[1]));
}

// fast exp2 on FMA pipe, rel err ~2e-6
__device__ __forceinline__ float exp2f_fast(float z) {
    z = fmaxf(z, -126.f);
    float r = z + 12582912.f;
    int   n = __float_as_int(r);
    float f = z - (r - 12582912.f);
    float p = 1.3333558146e-3f;
    p = fmaf(p, f, 9.6180216e-3f);
    p = fmaf(p, f, 5.5504109e-2f);
    p = fmaf(p, f, 2.4022651e-1f);
    p = fmaf(p, f, 6.9314718e-1f);
    p = fmaf(p, f, 1.0f);
    return __int_as_float(__float_as_int(p) + (n << 23));
}

// ===================== prepass: bf16 hi/lo split =====================
__global__ __launch_bounds__(256) void split_bf(const float* __restrict__ src,
                                                __nv_bfloat16* __restrict__ hi,
                                                __nv_bfloat16* __restrict__ lo, int n4) {
    int i = blockIdx.x * 256 + threadIdx.x;
    if (i >= n4) return;
    float4 v = ((const float4*)src)[i];
    __nv_bfloat16 h0 = __float2bfloat16(v.x), h1 = __float2bfloat16(v.y);
    __nv_bfloat16 h2 = __float2bfloat16(v.z), h3 = __float2bfloat16(v.w);
    __nv_bfloat16 l0 = __float2bfloat16(v.x - __bfloat162float(h0));
    __nv_bfloat16 l1 = __float2bfloat16(v.y - __bfloat162float(h1));
    __nv_bfloat16 l2 = __float2bfloat16(v.z - __bfloat162float(h2));
    __nv_bfloat16 l3 = __float2bfloat16(v.w - __bfloat162float(h3));
    __nv_bfloat162 hp0 = {h0, h1}, hp1 = {h2, h3}, lp0 = {l0, l1}, lp1 = {l2, l3};
    ((__nv_bfloat162*)hi)[2 * i]     = hp0;
    ((__nv_bfloat162*)hi)[2 * i + 1] = hp1;
    ((__nv_bfloat162*)lo)[2 * i]     = lp0;
    ((__nv_bfloat162*)lo)[2 * i + 1] = lp1;
}

// ===================== split-bf16 GEMM =====================
// C[M,N] = (A @ W^T + bias)*scale;  A=Ah+Al, W=Wh+Wl (bf16), 3-term mma16.
// 128x128 tile, k-chunk 32, 8 warps (2x4), double-buffered cp.async, 2 CTA/SM.
#define GB_STR   20                 // uint32 words per 32-bf16 row (pad 8 bf16)
#define GB_TILE  (128 * GB_STR)     // 2560 words
#define GB_STAGE (4 * GB_TILE)      // 10240 words
#define GB_SMEM  ((2 * GB_STAGE + 128) * 4)

__global__ __launch_bounds__(256, 2) void gemm_bf(
    const __nv_bfloat16* __restrict__ Ah, const __nv_bfloat16* __restrict__ Al,
    const __nv_bfloat16* __restrict__ Wh, const __nv_bfloat16* __restrict__ Wl,
    const float* __restrict__ bias, float* __restrict__ C,
    float scale, int doRound)
{
    extern __shared__ uint32_t smw[];
    float* bias_s = (float*)(smw + 2 * GB_STAGE);
    const int tid = threadIdx.x, lane = tid & 31, wid = tid >> 5;
    const int row0 = blockIdx.y * 128, col0 = blockIdx.x * 128;
    const uint32_t sbase = (uint32_t)__cvta_generic_to_shared(smw);
    const int m0w = (wid >> 2) * 64, n0w = (wid & 3) * 32;

    if (tid < 128) bias_s[tid] = bias[col0 + tid];

    float acc[4][4][4];
#pragma unroll
    for (int a = 0; a < 4; a++)
#pragma unroll
        for (int b = 0; b < 4; b++)
#pragma unroll
            for (int c = 0; c < 4; c++) acc[a][b][c] = 0.f;

    const __nv_bfloat16* srcs[4] = {Ah, Al, Wh, Wl};
    const int rbase[4] = {row0, row0, col0, col0};

    // prologue chunk 0 -> stage 0 (each tile: 128 rows x 2 x 16B)
#pragma unroll
    for (int tl = 0; tl < 4; tl++) {
#pragma unroll
        for (int j = 0; j < 2; j++) {
            int id = tid + 256 * j, r = id >> 2, c4 = id & 3;
            cp16(sbase + (uint32_t)(tl * GB_TILE + r * GB_STR + c4 * 4) * 4u,
                 srcs[tl] + (size_t)(rbase[tl] + r) * D_ + c4 * 8);
        }
    }
    CP_COMMIT();

    for (int ch = 0; ch < D_ / 32; ch++) {
        const int s = ch & 1;
        CP_WAIT0();
        __syncthreads();
        if (ch + 1 < D_ / 32) {
            const uint32_t so = (uint32_t)((s ^ 1) * GB_STAGE) * 4u;
            const int k1 = (ch + 1) * 32;
#pragma unroll
            for (int tl = 0; tl < 4; tl++) {
#pragma unroll
                for (int j = 0; j < 2; j++) {
                    int id = tid + 256 * j, r = id >> 2, c4 = id & 3;
                    cp16(sbase + so + (uint32_t)(tl * GB_TILE + r * GB_STR + c4 * 4) * 4u,
                         srcs[tl] + (size_t)(rbase[tl] + r) * D_ + k1 + c4 * 8);
                }
            }
            CP_COMMIT();
        }
        const uint32_t* sAh = smw + s * GB_STAGE;
        const uint32_t* sAl = sAh + GB_TILE;
        const uint32_t* sBh = sAl + GB_TILE;
        const uint32_t* sBl = sBh + GB_TILE;

#pragma unroll
        for (int ks = 0; ks < 2; ks++) {
            const int kw = ks * 8 + (lane & 3);
            uint32_t ah[4][4], al[4][4], bh[4][2], bl[4][2];
#pragma unroll
            for (int mt = 0; mt < 4; mt++) {
                const int m = m0w + mt * 16 + (lane >> 2);
                ah[mt][0] = sAh[m * GB_STR + kw];
                ah[mt][1] = sAh[(m + 8) * GB_STR + kw];
                ah[mt][2] = sAh[m * GB_STR + kw + 4];
                ah[mt][3] = sAh[(m + 8) * GB_STR + kw + 4];
                al[mt][0] = sAl[m * GB_STR + kw];
                al[mt][1] = sAl[(m + 8) * GB_STR + kw];
                al[mt][2] = sAl[m * GB_STR + kw + 4];
                al[mt][3] = sAl[(m + 8) * GB_STR + kw + 4];
            }
#pragma unroll
            for (int nt = 0; nt < 4; nt++) {
                const int n = n0w + nt * 8 + (lane >> 2);
                bh[nt][0] = sBh[n * GB_STR + kw];
                bh[nt][1] = sBh[n * GB_STR + kw + 4];
                bl[nt][0] = sBl[n * GB_STR + kw];
                bl[nt][1] = sBl[n * GB_STR + kw + 4];
            }
#pragma unroll
            for (int mt = 0; mt < 4; mt++)
#pragma unroll
                for (int nt = 0; nt < 4; nt++) {
                    mma16(acc[mt][nt], ah[mt], bh[nt]);
                    mma16(acc[mt][nt], al[mt], bh[nt]);
                    mma16(acc[mt][nt], ah[mt], bl[nt]);
                }
        }
    }

#pragma unroll
    for (int mt = 0; mt < 4; mt++) {
        const int r = row0 + m0w + mt * 16 + (lane >> 2);
#pragma unroll
        for (int nt = 0; nt < 4; nt++) {
            const int cc = n0w + nt * 8 + 2 * (lane & 3);
            float v0 = (acc[mt][nt][0] + bias_s[cc]) * scale;
            float v1 = (acc[mt][nt][1] + bias_s[cc + 1]) * scale;
            float v2 = (acc[mt][nt][2] + bias_s[cc]) * scale;
            float v3 = (acc[mt][nt][3] + bias_s[cc + 1]) * scale;
            if (doRound) {
                v0 = to_tf32(v0); v1 = to_tf32(v1);
                v2 = to_tf32(v2); v3 = to_tf32(v3);
            }
            *(float2*)&C[(size_t)r * D_ + col0 + cc] = make_float2(v0, v1);
            *(float2*)&C[(size_t)(r + 8) * D_ + col0 + cc] = make_float2(v2, v3);
        }
    }
}

// ===================== mma flash attention (tf32) =====================
#define QS(r, c) (A_QS + (r) * 128 + ((c) ^ (((r) & 7) << 2)))
#define KS(st, r, c) (A_KS + (st) * 8192 + (r) * 128 + ((c) ^ (((r) & 7) << 2)))
#define VS(st, r, c) (A_VS + (st) * 8192 + (r) * 128 + ((c) ^ (((r) & 7) << 2)))
#define SS(r, c) (A_SS + (r) * 64 + ((c) ^ (((r) & 7) << 2)))
#define A_QS 0
#define A_KS 16384
#define A_VS 32768
#define A_SS 49152
#define A_MR 57344
#define A_LR 57472
#define A_SR 57600
#define ATTN_SMEM (57728 * 4)

__global__ __launch_bounds__(256) void attn_tc()
{
    extern __shared__ float sm[];
    const int tid = threadIdx.x, lane = tid & 31, wid = tid >> 5;
    const int wR = wid >> 1, wC = wid & 1;
    const int q0 = blockIdx.x * 128, h = blockIdx.y, b = blockIdx.z;
    const uint32_t sbase = (uint32_t)__cvta_generic_to_shared(sm);
    const size_t gbase = (size_t)b * S_ * D_ + (size_t)h * HD_;

    if (tid < 128) { sm[A_MR + tid] = -1e30f; sm[A_LR + tid] = 0.f; }

#pragma unroll
    for (int j = 0; j < 16; j++) {
        int id = tid + 256 * j, r = id >> 5, c4 = id & 31;
        cp16(sbase + (uint32_t)QS(r, c4 * 4) * 4u,
             &g_q[gbase + (size_t)(q0 + r) * D_ + c4 * 4]);
    }
#pragma unroll
    for (int j = 0; j < 8; j++) {
        int id = tid + 256 * j, r = id >> 5, c4 = id & 31;
        cp16(sbase + (uint32_t)KS(0, r, c4 * 4) * 4u,
             &g_k[gbase + (size_t)r * D_ + c4 * 4]);
        cp16(sbase + (uint32_t)VS(0, r, c4 * 4) * 4u,
             &g_v[gbase + (size_t)r * D_ + c4 * 4]);
    }
    CP_COMMIT();

    float oacc[2][8][4];
#pragma unroll
    for (int a = 0; a < 2; a++)
#pragma unroll
        for (int c = 0; c < 8; c++)
#pragma unroll
            for (int e = 0; e < 4; e++) oacc[a][c][e] = 0.f;

    const int ntiles = q0 / 64 + 2;
    for (int t = 0; t < ntiles; t++) {
        const int s = t & 1;
        const int kv0 = t * 64;
        CP_WAIT0();
        __syncthreads();
        if (t + 1 < ntiles) {
            const size_t kr = gbase + (size_t)(kv0 + 64) * D_;
#pragma unroll
            for (int j = 0; j < 8; j++) {
                int id = tid + 256 * j, r = id >> 5, c4 = id & 31;
                cp16(sbase + (uint32_t)KS(s ^ 1, r, c4 * 4) * 4u,
                     &g_k[kr + (size_t)r * D_ + c4 * 4]);
                cp16(sbase + (uint32_t)VS(s ^ 1, r, c4 * 4) * 4u,
                     &g_v[kr + (size_t)r * D_ + c4 * 4]);
            }
            CP_COMMIT();
        }

        float sacc[2][4][4];
#pragma unroll
        for (int a = 0; a < 2; a++)
#pragma unroll
            for (int c = 0; c < 4; c++)
#pragma unroll
                for (int e = 0; e < 4; e++) sacc[a][c][e] = 0.f;

#pragma unroll
        for (int ks = 0; ks < 16; ks++) {
            const int kb = ks * 8, k = kb + (lane & 3);
            uint32_t aq[2][4], bk[4][2];
#pragma unroll
            for (int mt = 0; mt < 2; mt++) {
                const int r = wR * 32 + mt * 16 + (lane >> 2);
                aq[mt][0] = __float_as_uint(sm[QS(r, k)]);
                aq[mt][1] = __float_as_uint(sm[QS(r + 8, k)]);
                aq[mt][2] = __float_as_uint(sm[QS(r, k + 4)]);
                aq[mt][3] = __float_as_uint(sm[QS(r + 8, k + 4)]);
            }
#pragma unroll
            for (int nt = 0; nt < 4; nt++) {
                const int n = wC * 32 + nt * 8 + (lane >> 2);
                bk[nt][0] = __float_as_uint(sm[KS(s, n, k)]);
                bk[nt][1] = __float_as_uint(sm[KS(s, n, k + 4)]);
            }
#pragma unroll
            for (int mt = 0; mt < 2; mt++)
#pragma unroll
                for (int nt = 0; nt < 4; nt++)
                    mma8(sacc[mt][nt], aq[mt], bk[nt]);
        }

#pragma unroll
        for (int mt = 0; mt < 2; mt++) {
            const int rl = wR * 32 + mt * 16 + (lane >> 2);
#pragma unroll
            for (int nt = 0; nt < 4; nt++) {
                const int cl_ = wC * 32 + nt * 8 + 2 * (lane & 3);
                float e0 = (kv0 + cl_     <= q0 + rl)     ? sacc[mt][nt][0] : -1e30f;
                float e1 = (kv0 + cl_ + 1 <= q0 + rl)     ? sacc[mt][nt][1] : -1e30f;
                float e2 = (kv0 + cl_     <= q0 + rl + 8) ? sacc[mt][nt][2] : -1e30f;
                float e3 = (kv0 + cl_ + 1 <= q0 + rl + 8) ? sacc[mt][nt][3] : -1e30f;
                *(float2*)&sm[SS(rl, cl_)]     = make_float2(e0, e1);
                *(float2*)&sm[SS(rl + 8, cl_)] = make_float2(e2, e3);
            }
        }
        __syncthreads();

        {
            const int r = tid >> 1, cb = (tid & 1) * 32;
            float mx = -1e30f;
#pragma unroll
            for (int i = 0; i < 8; i++) {
                float4 v = *(const float4*)&sm[SS(r, cb + i * 4)];
                mx = fmaxf(mx, fmaxf(fmaxf(v.x, v.y), fmaxf(v.z, v.w)));
            }
            mx = fmaxf(mx, __shfl_xor_sync(0xffffffffu, mx, 1));
            const float mold = sm[A_MR + r];
            const float mnew = fmaxf(mold, mx);
            const float msl  = mnew * LOG2E;
            float sum = 0.f;
#pragma unroll
            for (int i = 0; i < 8; i++) {
                float4 v = *(const float4*)&sm[SS(r, cb + i * 4)];
                v.x = to_tf32(exp2f_fast(fmaf(v.x, LOG2E, -msl)));
                v.y = to_tf32(exp2f_fast(fmaf(v.y, LOG2E, -msl)));
                v.z = to_tf32(exp2f_fast(fmaf(v.z, LOG2E, -msl)));
                v.w = to_tf32(exp2f_fast(fmaf(v.w, LOG2E, -msl)));
                *(float4*)&sm[SS(r, cb + i * 4)] = v;
                sum += v.x + v.y + v.z + v.w;
            }
            sum += __shfl_xor_sync(0xffffffffu, sum, 1);
            if ((tid & 1) == 0) {
                const float scl = exp2f_fast((mold - mnew) * LOG2E);
                sm[A_MR + r] = mnew;
                sm[A_SR + r] = scl;
                sm[A_LR + r] = sm[A_LR + r] * scl + sum;
            }
        }
        __syncthreads();

#pragma unroll
        for (int mt = 0; mt < 2; mt++) {
            const int rl = wR * 32 + mt * 16 + (lane >> 2);
            const float s0 = sm[A_SR + rl], s1 = sm[A_SR + rl + 8];
#pragma unroll
            for (int nt = 0; nt < 8; nt++) {
                oacc[mt][nt][0] *= s0; oacc[mt][nt][1] *= s0;
                oacc[mt][nt][2] *= s1; oacc[mt][nt][3] *= s1;
            }
        }
#pragma unroll
        for (int ks = 0; ks < 8; ks++) {
            const int kb = ks * 8, k = kb + (lane & 3);
            uint32_t ap[2][4], bv[8][2];
#pragma unroll
            for (int mt = 0; mt < 2; mt++) {
                const int r = wR * 32 + mt * 16 + (lane >> 2);
                ap[mt][0] = __float_as_uint(sm[SS(r, k)]);
                ap[mt][1] = __float_as_uint(sm[SS(r + 8, k)]);
                ap[mt][2] = __float_as_uint(sm[SS(r, k + 4)]);
                ap[mt][3] = __float_as_uint(sm[SS(r + 8, k + 4)]);
            }
#pragma unroll
            for (int nt = 0; nt < 8; nt++) {
                const int n = wC * 64 + nt * 8 + (lane >> 2);
                bv[nt][0] = __float_as_uint(sm[VS(s, k, n)]);
                bv[nt][1] = __float_as_uint(sm[VS(s, k + 4, n)]);
            }
#pragma unroll
            for (int mt = 0; mt < 2; mt++)
#pragma unroll
                for (int nt = 0; nt < 8; nt++)
                    mma8(oacc[mt][nt], ap[mt], bv[nt]);
        }
    }

    // epilogue: normalize, bf16 hi/lo split, write ctx
#pragma unroll
    for (int mt = 0; mt < 2; mt++) {
        const int rl = wR * 32 + mt * 16 + (lane >> 2);
        const float i0 = 1.f / sm[A_LR + rl], i1 = 1.f / sm[A_LR + rl + 8];
        const size_t r0a = gbase + (size_t)(q0 + rl) * D_;
        const size_t r1a = gbase + (size_t)(q0 + rl + 8) * D_;
#pragma unroll
        for (int nt = 0; nt < 8; nt++) {
            const int dd = wC * 64 + nt * 8 + 2 * (lane & 3);
            float v0 = oacc[mt][nt][0] * i0, v1 = oacc[mt][nt][1] * i0;
            float v2 = oacc[mt][nt][2] * i1, v3 = oacc[mt][nt][3] * i1;
            __nv_bfloat16 h0 = __float2bfloat16(v0), h1 = __float2bfloat16(v1);
            __nv_bfloat16 h2 = __float2bfloat16(v2), h3 = __float2bfloat16(v3);
            __nv_bfloat162 hp0 = {h0, h1}, hp1 = {h2, h3};
            __nv_bfloat162 lp0 = {__float2bfloat16(v0 - __bfloat162float(h0)),
                                  __float2bfloat16(v1 - __bfloat162float(h1))};
            __nv_bfloat162 lp1 = {__float2bfloat16(v2 - __bfloat162float(h2)),
                                  __float2bfloat16(v3 - __bfloat162float(h3))};
            *(__nv_bfloat162*)&g_ch[r0a + dd] = hp0;
            *(__nv_bfloat162*)&g_ch[r1a + dd] = hp1;
            *(__nv_bfloat162*)&g_cl[r0a + dd] = lp0;
            *(__nv_bfloat162*)&g_cl[r1a + dd] = lp1;
        }
    }
}

// ===================== launcher =====================
extern "C" void kernel_launch(void* const* d_in, const int* in_sizes, int n_in,
                              void* d_out, int out_size)
{
    const float* x  = (const float*)d_in[0];
    const float* Wq = (const float*)d_in[1];
    const float* bq = (const float*)d_in[2];
    const float* Wk = (const float*)d_in[3];
    const float* bk = (const float*)d_in[4];
    const float* Wv = (const float*)d_in[5];
    const float* bv = (const float*)d_in[6];
    const float* Wo = (const float*)d_in[7];
    const float* bo = (const float*)d_in[8];
    float* out = (float*)d_out;

    __nv_bfloat16 *xh, *xl, *wh, *wl, *chp, *clp;
    float *qp, *kp, *vp;
    cudaGetSymbolAddress((void**)&xh, g_xh);
    cudaGetSymbolAddress((void**)&xl, g_xl);
    cudaGetSymbolAddress((void**)&wh, g_wh);
    cudaGetSymbolAddress((void**)&wl, g_wl);
    cudaGetSymbolAddress((void**)&qp, g_q);
    cudaGetSymbolAddress((void**)&kp, g_k);
    cudaGetSymbolAddress((void**)&vp, g_v);
    cudaGetSymbolAddress((void**)&chp, g_ch);
    cudaGetSymbolAddress((void**)&clp, g_cl);

    cudaFuncSetAttribute(gemm_bf,
                         cudaFuncAttributeMaxDynamicSharedMemorySize, GB_SMEM);
    cudaFuncSetAttribute(attn_tc,
                         cudaFuncAttributeMaxDynamicSharedMemorySize, ATTN_SMEM);

    split_bf<<<(BS_D / 4 + 255) / 256, 256>>>(x, xh, xl, BS_D / 4);
    split_bf<<<(WSZ / 4 + 255) / 256, 256>>>(Wq, wh + 0 * WSZ, wl + 0 * WSZ, WSZ / 4);
    split_bf<<<(WSZ / 4 + 255) / 256, 256>>>(Wk, wh + 1 * WSZ, wl + 1 * WSZ, WSZ / 4);
    split_bf<<<(WSZ / 4 + 255) / 256, 256>>>(Wv, wh + 2 * WSZ, wl + 2 * WSZ, WSZ / 4);
    split_bf<<<(WSZ / 4 + 255) / 256, 256>>>(Wo, wh + 3 * WSZ, wl + 3 * WSZ, WSZ / 4);

    const dim3 gg(D_ / 128, M_ / 128);            // (16, 32)
    const float qscale = 0.08838834764831845f;    // 1/sqrt(HD)
    gemm_bf<<<gg, 256, GB_SMEM>>>(xh, xl, wh + 0 * WSZ, wl + 0 * WSZ, bq, qp, qscale, 1);
    gemm_bf<<<gg, 256, GB_SMEM>>>(xh, xl, wh + 1 * WSZ, wl + 1 * WSZ, bk, kp, 1.f, 1);
    gemm_bf<<<gg, 256, GB_SMEM>>>(xh, xl, wh + 2 * WSZ, wl + 2 * WSZ, bv, vp, 1.f, 1);

    const dim3 ga(S_ / 128, H_, B_);              // (16, 16, 2)
    attn_tc<<<ga, 256, ATTN_SMEM>>>();

    gemm_bf<<<gg, 256, GB_SMEM>>>(chp, clp, wh + 3 * WSZ, wl + 3 * WSZ, bo, out, 1.f, 0);
}

// round 6
// speedup vs baseline: 3.5100x; 1.1409x over previous
#include <cuda_runtime.h>
#include <cuda_bf16.h>
#include <cstdint>
#include <math.h>

#define B_  2
#define S_  2048
#define D_  2048
#define H_  16
#define HD_ 128
#define M_  (B_ * S_)
#define BS_D (B_ * S_ * D_)
#define WSZ (D_ * D_)
#define LOG2E 1.4426950408889634f

// Scratch (device globals — no allocation allowed)
__device__ __align__(16) __nv_bfloat16 g_xh[BS_D], g_xl[BS_D];
__device__ __align__(16) __nv_bfloat16 g_wh[4 * WSZ], g_wl[4 * WSZ];
__device__ __align__(16) float g_q[BS_D], g_k[BS_D], g_v[BS_D];
__device__ __align__(16) __nv_bfloat16 g_ch[BS_D], g_cl[BS_D];

// ===================== helpers =====================
__device__ __forceinline__ float to_tf32(float x) {
    float y;
    asm("cvt.rna.tf32.f32 %0, %1;" : "=f"(y) : "f"(x));
    return y;
}
__device__ __forceinline__ void cp16(uint32_t dst, const void* src) {
    asm volatile("cp.async.cg.shared.global [%0], [%1], 16;"
                 :: "r"(dst), "l"(src) : "memory");
}
#define CP_COMMIT() asm volatile("cp.async.commit_group;" ::: "memory")
#define CP_WAIT0()  asm volatile("cp.async.wait_group 0;" ::: "memory")

__device__ __forceinline__ void ldm_x4(uint32_t* r, uint32_t addr) {
    asm volatile("ldmatrix.sync.aligned.m8n8.x4.shared.b16 {%0,%1,%2,%3}, [%4];"
                 : "=r"(r[0]), "=r"(r[1]), "=r"(r[2]), "=r"(r[3]) : "r"(addr));
}

// tf32 m16n8k8 (attention)
__device__ __forceinline__ void mma8(float* d, const uint32_t* a, const uint32_t* b) {
    asm volatile("mma.sync.aligned.m16n8k8.row.col.f32.tf32.tf32.f32 "
                 "{%0,%1,%2,%3}, {%4,%5,%6,%7}, {%8,%9}, {%0,%1,%2,%3};"
                 : "+f"(d[0]), "+f"(d[1]), "+f"(d[2]), "+f"(d[3])
                 : "r"(a[0]), "r"(a[1]), "r"(a[2]), "r"(a[3]),
                   "r"(b[0]), "r"(b[1]));
}
// bf16 m16n8k16 (GEMMs)
__device__ __forceinline__ void mma16(float* d, const uint32_t* a, const uint32_t* b) {
    asm volatile("mma.sync.aligned.m16n8k16.row.col.f32.bf16.bf16.f32 "
                 "{%0,%1,%2,%3}, {%4,%5,%6,%7}, {%8,%9}, {%0,%1,%2,%3};"
                 : "+f"(d[0]), "+f"(d[1]), "+f"(d[2]), "+f"(d[3])
                 : "r"(a[0]), "r"(a[1]), "r"(a[2]), "r"(a[3]),
                   "r"(b[0]), "r"(b[1]));
}

// fast exp2 on FMA pipe
__device__ __forceinline__ float exp2f_fast(float z) {
    z = fmaxf(z, -126.f);
    float r = z + 12582912.f;
    int   n = __float_as_int(r);
    float f = z - (r - 12582912.f);
    float p = 1.3333558146e-3f;
    p = fmaf(p, f, 9.6180216e-3f);
    p = fmaf(p, f, 5.5504109e-2f);
    p = fmaf(p, f, 2.4022651e-1f);
    p = fmaf(p, f, 6.9314718e-1f);
    p = fmaf(p, f, 1.0f);
    return __int_as_float(__float_as_int(p) + (n << 23));
}

// ===================== fused prepass: bf16 hi/lo split (x + 4 W) =====================
#define N4X (BS_D / 4)
#define N4W (WSZ / 4)
__global__ __launch_bounds__(256) void split_all(
    const float* __restrict__ x,  const float* __restrict__ Wq,
    const float* __restrict__ Wk, const float* __restrict__ Wv,
    const float* __restrict__ Wo)
{
    int i = blockIdx.x * 256 + threadIdx.x;
    const float* src;
    __nv_bfloat16 *hi, *lo;
    int j;
    if (i < N4X) { src = x; hi = g_xh; lo = g_xl; j = i; }
    else {
        int w = (i - N4X) / N4W;         // 0..3
        j = (i - N4X) - w * N4W;
        src = (w == 0) ? Wq : (w == 1) ? Wk : (w == 2) ? Wv : Wo;
        hi = g_wh + w * WSZ; lo = g_wl + w * WSZ;
    }
    float4 v = ((const float4*)src)[j];
    __nv_bfloat16 h0 = __float2bfloat16(v.x), h1 = __float2bfloat16(v.y);
    __nv_bfloat16 h2 = __float2bfloat16(v.z), h3 = __float2bfloat16(v.w);
    __nv_bfloat162 hp0 = {h0, h1}, hp1 = {h2, h3};
    __nv_bfloat162 lp0 = {__float2bfloat16(v.x - __bfloat162float(h0)),
                          __float2bfloat16(v.y - __bfloat162float(h1))};
    __nv_bfloat162 lp1 = {__float2bfloat16(v.z - __bfloat162float(h2)),
                          __float2bfloat16(v.w - __bfloat162float(h3))};
    ((__nv_bfloat162*)hi)[2 * j]     = hp0;
    ((__nv_bfloat162*)hi)[2 * j + 1] = hp1;
    ((__nv_bfloat162*)lo)[2 * j]     = lp0;
    ((__nv_bfloat162*)lo)[2 * j + 1] = lp1;
}

// ===================== split-bf16 GEMM (ldmatrix + merged QKV) =====================
#define GB_STR   20                 // uint32 words per 32-bf16 row (pad 8 bf16)
#define GB_TILE  (128 * GB_STR)
#define GB_STAGE (4 * GB_TILE)
#define GB_SMEM  ((2 * GB_STAGE + 128) * 4)

struct GemmJob { const __nv_bfloat16 *Ah, *Al, *Wh, *Wl; const float* bias;
                 float* C; float scale; int doRound; };

__device__ __forceinline__ void gemm_body(const GemmJob& jb, int bx, int by)
{
    extern __shared__ uint32_t smw[];
    float* bias_s = (float*)(smw + 2 * GB_STAGE);
    const int tid = threadIdx.x, lane = tid & 31, wid = tid >> 5;
    const int row0 = by * 128, col0 = bx * 128;
    const uint32_t sbase = (uint32_t)__cvta_generic_to_shared(smw);
    const int m0w = (wid >> 2) * 64, n0w = (wid & 3) * 32;

    if (tid < 128) bias_s[tid] = jb.bias[col0 + tid];

    float acc[4][4][4];
#pragma unroll
    for (int a = 0; a < 4; a++)
#pragma unroll
        for (int b = 0; b < 4; b++)
#pragma unroll
            for (int c = 0; c < 4; c++) acc[a][b][c] = 0.f;

    const __nv_bfloat16* srcs[4] = {jb.Ah, jb.Al, jb.Wh, jb.Wl};
    const int rbase[4] = {row0, row0, col0, col0};

#pragma unroll
    for (int tl = 0; tl < 4; tl++)
#pragma unroll
        for (int j = 0; j < 2; j++) {
            int id = tid + 256 * j, r = id >> 2, c4 = id & 3;
            cp16(sbase + (uint32_t)(tl * GB_TILE + r * GB_STR + c4 * 4) * 4u,
                 srcs[tl] + (size_t)(rbase[tl] + r) * D_ + c4 * 8);
        }
    CP_COMMIT();

    // ldmatrix lane address components
    const int lq  = lane >> 3;            // matrix index 0..3
    const int lr  = lane & 7;             // row within matrix
    const int aRow = (lq & 1) * 8 + lr;   // +0/+8 row
    const int aKof = (lq >> 1) * 4;       // +0/+8 bf16 -> +4 words

    for (int ch = 0; ch < D_ / 32; ch++) {
        const int s = ch & 1;
        CP_WAIT0();
        __syncthreads();
        if (ch + 1 < D_ / 32) {
            const uint32_t so = (uint32_t)((s ^ 1) * GB_STAGE) * 4u;
            const int k1 = (ch + 1) * 32;
#pragma unroll
            for (int tl = 0; tl < 4; tl++)
#pragma unroll
                for (int j = 0; j < 2; j++) {
                    int id = tid + 256 * j, r = id >> 2, c4 = id & 3;
                    cp16(sbase + so + (uint32_t)(tl * GB_TILE + r * GB_STR + c4 * 4) * 4u,
                         srcs[tl] + (size_t)(rbase[tl] + r) * D_ + k1 + c4 * 8);
                }
            CP_COMMIT();
        }
        const uint32_t stage = sbase + (uint32_t)(s * GB_STAGE) * 4u;
        const uint32_t sAh = stage;
        const uint32_t sAl = stage + GB_TILE * 4u;
        const uint32_t sBh = stage + 2u * GB_TILE * 4u;
        const uint32_t sBl = stage + 3u * GB_TILE * 4u;

#pragma unroll
        for (int ks = 0; ks < 2; ks++) {
            const uint32_t kwo = (uint32_t)(ks * 8 + aKof) * 4u;
            uint32_t ah[4][4], al[4][4], bh[4][2], bl[4][2];
#pragma unroll
            for (int mt = 0; mt < 4; mt++) {
                const uint32_t ro = (uint32_t)((m0w + mt * 16 + aRow) * GB_STR) * 4u;
                ldm_x4(ah[mt], sAh + ro + kwo);
                ldm_x4(al[mt], sAl + ro + kwo);
            }
            // B: x4 covers two n8 tiles (q<2 -> nt, q>=2 -> nt+1)
            const uint32_t bro = (uint32_t)(((lq >> 1) * 8 + lr) * GB_STR) * 4u;
            const uint32_t bko = (uint32_t)(ks * 8 + (lq & 1) * 4) * 4u;
#pragma unroll
            for (int np = 0; np < 2; np++) {
                const uint32_t nb = (uint32_t)((n0w + np * 16) * GB_STR) * 4u;
                uint32_t t[4];
                ldm_x4(t, sBh + nb + bro + bko);
                bh[np*2][0] = t[0]; bh[np*2][1] = t[1];
                bh[np*2+1][0] = t[2]; bh[np*2+1][1] = t[3];
                ldm_x4(t, sBl + nb + bro + bko);
                bl[np*2][0] = t[0]; bl[np*2][1] = t[1];
                bl[np*2+1][0] = t[2]; bl[np*2+1][1] = t[3];
            }
#pragma unroll
            for (int mt = 0; mt < 4; mt++)
#pragma unroll
                for (int nt = 0; nt < 4; nt++) {
                    mma16(acc[mt][nt], ah[mt], bh[nt]);
                    mma16(acc[mt][nt], al[mt], bh[nt]);
                    mma16(acc[mt][nt], ah[mt], bl[nt]);
                }
        }
    }

#pragma unroll
    for (int mt = 0; mt < 4; mt++) {
        const int r = row0 + m0w + mt * 16 + (lane >> 2);
#pragma unroll
        for (int nt = 0; nt < 4; nt++) {
            const int cc = n0w + nt * 8 + 2 * (lane & 3);
            float v0 = (acc[mt][nt][0] + bias_s[cc]) * jb.scale;
            float v1 = (acc[mt][nt][1] + bias_s[cc + 1]) * jb.scale;
            float v2 = (acc[mt][nt][2] + bias_s[cc]) * jb.scale;
            float v3 = (acc[mt][nt][3] + bias_s[cc + 1]) * jb.scale;
            if (jb.doRound) {
                v0 = to_tf32(v0); v1 = to_tf32(v1);
                v2 = to_tf32(v2); v3 = to_tf32(v3);
            }
            *(float2*)&jb.C[(size_t)r * D_ + col0 + cc] = make_float2(v0, v1);
            *(float2*)&jb.C[(size_t)(r + 8) * D_ + col0 + cc] = make_float2(v2, v3);
        }
    }
}

// merged QKV: grid (16, 32, 3)
__global__ __launch_bounds__(256, 2) void gemm_qkv(
    const float* __restrict__ bq, const float* __restrict__ bk,
    const float* __restrict__ bv, float qscale)
{
    GemmJob jb;
    const int z = blockIdx.z;
    jb.Ah = g_xh; jb.Al = g_xl;
    jb.Wh = g_wh + z * WSZ; jb.Wl = g_wl + z * WSZ;
    jb.bias = (z == 0) ? bq : (z == 1) ? bk : bv;
    jb.C = (z == 0) ? g_q : (z == 1) ? g_k : g_v;
    jb.scale = (z == 0) ? qscale : 1.f;
    jb.doRound = 1;
    gemm_body(jb, blockIdx.x, blockIdx.y);
}

__global__ __launch_bounds__(256, 2) void gemm_out(
    const float* __restrict__ bo, float* __restrict__ out)
{
    GemmJob jb;
    jb.Ah = g_ch; jb.Al = g_cl;
    jb.Wh = g_wh + 3 * WSZ; jb.Wl = g_wl + 3 * WSZ;
    jb.bias = bo; jb.C = out; jb.scale = 1.f; jb.doRound = 0;
    gemm_body(jb, blockIdx.x, blockIdx.y);
}

// ===================== mma flash attention (tf32, unchanged) =====================
#define QS(r, c) (A_QS + (r) * 128 + ((c) ^ (((r) & 7) << 2)))
#define KS(st, r, c) (A_KS + (st) * 8192 + (r) * 128 + ((c) ^ (((r) & 7) << 2)))
#define VS(st, r, c) (A_VS + (st) * 8192 + (r) * 128 + ((c) ^ (((r) & 7) << 2)))
#define SS(r, c) (A_SS + (r) * 64 + ((c) ^ (((r) & 7) << 2)))
#define A_QS 0
#define A_KS 16384
#define A_VS 32768
#define A_SS 49152
#define A_MR 57344
#define A_LR 57472
#define A_SR 57600
#define ATTN_SMEM (57728 * 4)

__global__ __launch_bounds__(256) void attn_tc()
{
    extern __shared__ float sm[];
    const int tid = threadIdx.x, lane = tid & 31, wid = tid >> 5;
    const int wR = wid >> 1, wC = wid & 1;
    const int q0 = blockIdx.x * 128, h = blockIdx.y, b = blockIdx.z;
    const uint32_t sbase = (uint32_t)__cvta_generic_to_shared(sm);
    const size_t gbase = (size_t)b * S_ * D_ + (size_t)h * HD_;

    if (tid < 128) { sm[A_MR + tid] = -1e30f; sm[A_LR + tid] = 0.f; }

#pragma unroll
    for (int j = 0; j < 16; j++) {
        int id = tid + 256 * j, r = id >> 5, c4 = id & 31;
        cp16(sbase + (uint32_t)QS(r, c4 * 4) * 4u,
             &g_q[gbase + (size_t)(q0 + r) * D_ + c4 * 4]);
    }
#pragma unroll
    for (int j = 0; j < 8; j++) {
        int id = tid + 256 * j, r = id >> 5, c4 = id & 31;
        cp16(sbase + (uint32_t)KS(0, r, c4 * 4) * 4u,
             &g_k[gbase + (size_t)r * D_ + c4 * 4]);
        cp16(sbase + (uint32_t)VS(0, r, c4 * 4) * 4u,
             &g_v[gbase + (size_t)r * D_ + c4 * 4]);
    }
    CP_COMMIT();

    float oacc[2][8][4];
#pragma unroll
    for (int a = 0; a < 2; a++)
#pragma unroll
        for (int c = 0; c < 8; c++)
#pragma unroll
            for (int e = 0; e < 4; e++) oacc[a][c][e] = 0.f;

    const int ntiles = q0 / 64 + 2;
    for (int t = 0; t < ntiles; t++) {
        const int s = t & 1;
        const int kv0 = t * 64;
        CP_WAIT0();
        __syncthreads();
        if (t + 1 < ntiles) {
            const size_t kr = gbase + (size_t)(kv0 + 64) * D_;
#pragma unroll
            for (int j = 0; j < 8; j++) {
                int id = tid + 256 * j, r = id >> 5, c4 = id & 31;
                cp16(sbase + (uint32_t)KS(s ^ 1, r, c4 * 4) * 4u,
                     &g_k[kr + (size_t)r * D_ + c4 * 4]);
                cp16(sbase + (uint32_t)VS(s ^ 1, r, c4 * 4) * 4u,
                     &g_v[kr + (size_t)r * D_ + c4 * 4]);
            }
            CP_COMMIT();
        }

        float sacc[2][4][4];
#pragma unroll
        for (int a = 0; a < 2; a++)
#pragma unroll
            for (int c = 0; c < 4; c++)
#pragma unroll
                for (int e = 0; e < 4; e++) sacc[a][c][e] = 0.f;

#pragma unroll
        for (int ks = 0; ks < 16; ks++) {
            const int kb = ks * 8, k = kb + (lane & 3);
            uint32_t aq[2][4], bk[4][2];
#pragma unroll
            for (int mt = 0; mt < 2; mt++) {
                const int r = wR * 32 + mt * 16 + (lane >> 2);
                aq[mt][0] = __float_as_uint(sm[QS(r, k)]);
                aq[mt][1] = __float_as_uint(sm[QS(r + 8, k)]);
                aq[mt][2] = __float_as_uint(sm[QS(r, k + 4)]);
                aq[mt][3] = __float_as_uint(sm[QS(r + 8, k + 4)]);
            }
#pragma unroll
            for (int nt = 0; nt < 4; nt++) {
                const int n = wC * 32 + nt * 8 + (lane >> 2);
                bk[nt][0] = __float_as_uint(sm[KS(s, n, k)]);
                bk[nt][1] = __float_as_uint(sm[KS(s, n, k + 4)]);
            }
#pragma unroll
            for (int mt = 0; mt < 2; mt++)
#pragma unroll
                for (int nt = 0; nt < 4; nt++)
                    mma8(sacc[mt][nt], aq[mt], bk[nt]);
        }

#pragma unroll
        for (int mt = 0; mt < 2; mt++) {
            const int rl = wR * 32 + mt * 16 + (lane >> 2);
#pragma unroll
            for (int nt = 0; nt < 4; nt++) {
                const int cl_ = wC * 32 + nt * 8 + 2 * (lane & 3);
                float e0 = (kv0 + cl_     <= q0 + rl)     ? sacc[mt][nt][0] : -1e30f;
                float e1 = (kv0 + cl_ + 1 <= q0 + rl)     ? sacc[mt][nt][1] : -1e30f;
                float e2 = (kv0 + cl_     <= q0 + rl + 8) ? sacc[mt][nt][2] : -1e30f;
                float e3 = (kv0 + cl_ + 1 <= q0 + rl + 8) ? sacc[mt][nt][3] : -1e30f;
                *(float2*)&sm[SS(rl, cl_)]     = make_float2(e0, e1);
                *(float2*)&sm[SS(rl + 8, cl_)] = make_float2(e2, e3);
            }
        }
        __syncthreads();

        {
            const int r = tid >> 1, cb = (tid & 1) * 32;
            float mx = -1e30f;
#pragma unroll
            for (int i = 0; i < 8; i++) {
                float4 v = *(const float4*)&sm[SS(r, cb + i * 4)];
                mx = fmaxf(mx, fmaxf(fmaxf(v.x, v.y), fmaxf(v.z, v.w)));
            }
            mx = fmaxf(mx, __shfl_xor_sync(0xffffffffu, mx, 1));
            const float mold = sm[A_MR + r];
            const float mnew = fmaxf(mold, mx);
            const float msl  = mnew * LOG2E;
            float sum = 0.f;
#pragma unroll
            for (int i = 0; i < 8; i++) {
                float4 v = *(const float4*)&sm[SS(r, cb + i * 4)];
                v.x = to_tf32(exp2f_fast(fmaf(v.x, LOG2E, -msl)));
                v.y = to_tf32(exp2f_fast(fmaf(v.y, LOG2E, -msl)));
                v.z = to_tf32(exp2f_fast(fmaf(v.z, LOG2E, -msl)));
                v.w = to_tf32(exp2f_fast(fmaf(v.w, LOG2E, -msl)));
                *(float4*)&sm[SS(r, cb + i * 4)] = v;
                sum += v.x + v.y + v.z + v.w;
            }
            sum += __shfl_xor_sync(0xffffffffu, sum, 1);
            if ((tid & 1) == 0) {
                const float scl = exp2f_fast((mold - mnew) * LOG2E);
                sm[A_MR + r] = mnew;
                sm[A_SR + r] = scl;
                sm[A_LR + r] = sm[A_LR + r] * scl + sum;
            }
        }
        __syncthreads();

#pragma unroll
        for (int mt = 0; mt < 2; mt++) {
            const int rl = wR * 32 + mt * 16 + (lane >> 2);
            const float s0 = sm[A_SR + rl], s1 = sm[A_SR + rl + 8];
#pragma unroll
            for (int nt = 0; nt < 8; nt++) {
                oacc[mt][nt][0] *= s0; oacc[mt][nt][1] *= s0;
                oacc[mt][nt][2] *= s1; oacc[mt][nt][3] *= s1;
            }
        }
#pragma unroll
        for (int ks = 0; ks < 8; ks++) {
            const int kb = ks * 8, k = kb + (lane & 3);
            uint32_t ap[2][4], bv[8][2];
#pragma unroll
            for (int mt = 0; mt < 2; mt++) {
                const int r = wR * 32 + mt * 16 + (lane >> 2);
                ap[mt][0] = __float_as_uint(sm[SS(r, k)]);
                ap[mt][1] = __float_as_uint(sm[SS(r + 8, k)]);
                ap[mt][2] = __float_as_uint(sm[SS(r, k + 4)]);
                ap[mt][3] = __float_as_uint(sm[SS(r + 8, k + 4)]);
            }
#pragma unroll
            for (int nt = 0; nt < 8; nt++) {
                const int n = wC * 64 + nt * 8 + (lane >> 2);
                bv[nt][0] = __float_as_uint(sm[VS(s, k, n)]);
                bv[nt][1] = __float_as_uint(sm[VS(s, k + 4, n)]);
            }
#pragma unroll
            for (int mt = 0; mt < 2; mt++)
#pragma unroll
                for (int nt = 0; nt < 8; nt++)
                    mma8(oacc[mt][nt], ap[mt], bv[nt]);
        }
    }

#pragma unroll
    for (int mt = 0; mt < 2; mt++) {
        const int rl = wR * 32 + mt * 16 + (lane >> 2);
        const float i0 = 1.f / sm[A_LR + rl], i1 = 1.f / sm[A_LR + rl + 8];
        const size_t r0a = gbase + (size_t)(q0 + rl) * D_;
        const size_t r1a = gbase + (size_t)(q0 + rl + 8) * D_;
#pragma unroll
        for (int nt = 0; nt < 8; nt++) {
            const int dd = wC * 64 + nt * 8 + 2 * (lane & 3);
            float v0 = oacc[mt][nt][0] * i0, v1 = oacc[mt][nt][1] * i0;
            float v2 = oacc[mt][nt][2] * i1, v3 = oacc[mt][nt][3] * i1;
            __nv_bfloat16 h0 = __float2bfloat16(v0), h1 = __float2bfloat16(v1);
            __nv_bfloat16 h2 = __float2bfloat16(v2), h3 = __float2bfloat16(v3);
            __nv_bfloat162 hp0 = {h0, h1}, hp1 = {h2, h3};
            __nv_bfloat162 lp0 = {__float2bfloat16(v0 - __bfloat162float(h0)),
                                  __float2bfloat16(v1 - __bfloat162float(h1))};
            __nv_bfloat162 lp1 = {__float2bfloat16(v2 - __bfloat162float(h2)),
                                  __float2bfloat16(v3 - __bfloat162float(h3))};
            *(__nv_bfloat162*)&g_ch[r0a + dd] = hp0;
            *(__nv_bfloat162*)&g_ch[r1a + dd] = hp1;
            *(__nv_bfloat162*)&g_cl[r0a + dd] = lp0;
            *(__nv_bfloat162*)&g_cl[r1a + dd] = lp1;
        }
    }
}

// ===================== launcher =====================
extern "C" void kernel_launch(void* const* d_in, const int* in_sizes, int n_in,
                              void* d_out, int out_size)
{
    const float* x  = (const float*)d_in[0];
    const float* Wq = (const float*)d_in[1];
    const float* bq = (const float*)d_in[2];
    const float* Wk = (const float*)d_in[3];
    const float* bk = (const float*)d_in[4];
    const float* Wv = (const float*)d_in[5];
    const float* bv = (const float*)d_in[6];
    const float* Wo = (const float*)d_in[7];
    const float* bo = (const float*)d_in[8];
    float* out = (float*)d_out;

    cudaFuncSetAttribute(gemm_qkv,
                         cudaFuncAttributeMaxDynamicSharedMemorySize, GB_SMEM);
    cudaFuncSetAttribute(gemm_out,
                         cudaFuncAttributeMaxDynamicSharedMemorySize, GB_SMEM);
    cudaFuncSetAttribute(attn_tc,
                         cudaFuncAttributeMaxDynamicSharedMemorySize, ATTN_SMEM);

    const int nTot = N4X + 4 * N4W;
    split_all<<<(nTot + 255) / 256, 256>>>(x, Wq, Wk, Wv, Wo);

    const float qscale = 0.08838834764831845f;    // 1/sqrt(HD)
    const dim3 gq(D_ / 128, M_ / 128, 3);         // (16, 32, 3)
    gemm_qkv<<<gq, 256, GB_SMEM>>>(bq, bk, bv, qscale);

    const dim3 ga(S_ / 128, H_, B_);              // (16, 16, 2)
    attn_tc<<<ga, 256, ATTN_SMEM>>>();

    const dim3 gg(D_ / 128, M_ / 128);            // (16, 32)
    gemm_out<<<gg, 256, GB_SMEM>>>(bo, out);
}